// round 14
// baseline (speedup 1.0000x reference)
#include <cuda_runtime.h>
#include <cuda_fp16.h>
#include <math.h>
#include <stdint.h>

#define D      256
#define KNBR   32
#define TOPK   16
#define MAXN   20096      // 157 * 128, padded
#define K2     512        // GEMM K = 2*D

// ---------------- scratch (__device__ globals; zero-init, no allocs) -------
__device__ __align__(128) __half g_Ah[(size_t)MAXN * K2];  // [row, 512] fp16
__device__ __align__(128) __half g_Bh[D * K2];             // [n, 512] fp16 (W^T)
__device__ float g_vs[D];
__device__ float g_vn[D];

__device__ __forceinline__ uint32_t smem_u32(const void* p) {
    uint32_t a;
    asm("{ .reg .u64 t; cvta.to.shared.u64 t, %1; cvt.u32.u64 %0, t; }" : "=r"(a) : "l"(p));
    return a;
}

// ---------------------------------------------------------------------------
// prep: GEMV only (16 blocks): v = W @ a.  (convB moved into phase1.)
// ---------------------------------------------------------------------------
__global__ void __launch_bounds__(256)
prep_kernel(const float* __restrict__ sw, const float* __restrict__ nw,
            const float* __restrict__ attn)
{
    const int b = blockIdx.x;
    const int t = threadIdx.x;

    __shared__ float a[D];
    const int wid = t >> 5, lane = t & 31;
    a[t] = attn[t];
    __syncthreads();

    const float* w = ((b & 1) == 0) ? sw : nw;
#pragma unroll
    for (int r = 0; r < 4; r++) {
        int row = (b >> 1) * 32 + wid * 4 + r;
        const float4* wr = (const float4*)(w + (size_t)row * D);
        float4 v0 = wr[lane], v1 = wr[lane + 32];
        float p = v0.x * a[4 * lane + 0] + v0.y * a[4 * lane + 1]
                + v0.z * a[4 * lane + 2] + v0.w * a[4 * lane + 3]
                + v1.x * a[128 + 4 * lane + 0] + v1.y * a[128 + 4 * lane + 1]
                + v1.z * a[128 + 4 * lane + 2] + v1.w * a[128 + 4 * lane + 3];
#pragma unroll
        for (int o = 16; o > 0; o >>= 1) p += __shfl_down_sync(0xffffffffu, p, o);
        if (lane == 0) { if ((b & 1) == 0) g_vs[row] = p; else g_vn[row] = p; }
    }
}

// ---------------------------------------------------------------------------
// Phase 1: per node — logits, softmax over 33, top-16, weighted neighbor sum.
// cp.async tile load overlapped with self-row work. Writes A fp16.
// Blocks 0..511 additionally convert their 256-element slice of B = W^T fp16
// (consumed only by the gemm kernel — stream order covers the dependency).
// ---------------------------------------------------------------------------
__global__ void __launch_bounds__(256)
phase1_kernel(const float* __restrict__ self_vecs,
              const float* __restrict__ neigh_vecs,
              const float* __restrict__ sw, const float* __restrict__ nw)
{
    __shared__ float4 tile[KNBR * D / 4];   // 32 KB
    __shared__ float4 vn4[D / 4];
    __shared__ float  dots[KNBR];
    __shared__ float  warp_part[8];
    __shared__ float  s_selflogit;
    __shared__ float  sel_w[TOPK];
    __shared__ int    sel_i[TOPK];

    const int n    = blockIdx.x;
    const int t    = threadIdx.x;
    const int wid  = t >> 5;
    const int lane = t & 31;

    const float4* src = (const float4*)(neigh_vecs + (size_t)n * KNBR * D);
#pragma unroll
    for (int i = 0; i < 8; i++) {
        uint32_t dst = smem_u32(&tile[t + 256 * i]);
        asm volatile("cp.async.cg.shared.global [%0], [%1], 16;"
                     :: "r"(dst), "l"((const void*)(src + t + 256 * i)));
    }
    asm volatile("cp.async.commit_group;");

    // convB appendix (blocks 0..511): same (n,k) mapping as the old prep
    if (n < 512) {
        int e  = n * 256 + t;                // 0 .. 131071
        int nb = e & 255;
        int k  = e >> 8;                     // 0 .. 511
        float w = (k < D) ? sw[(size_t)k * D + nb] : nw[(size_t)(k - D) * D + nb];
        g_Bh[(size_t)nb * K2 + k] = __float2half_rn(w);
    }

    if (t < D / 4) vn4[t] = ((const float4*)g_vn)[t];

    float sv = self_vecs[(size_t)n * D + t];
    g_Ah[(size_t)n * K2 + t] = __float2half_rn(sv);
    float sp = sv * g_vs[t];
#pragma unroll
    for (int o = 16; o > 0; o >>= 1) sp += __shfl_down_sync(0xffffffffu, sp, o);
    if (lane == 0) warp_part[wid] = sp;

    asm volatile("cp.async.wait_group 0;");
    __syncthreads();

#pragma unroll
    for (int r = 0; r < 4; r++) {
        int row = wid * 4 + r;
        float4 a0 = tile[row * 64 + lane];
        float4 a1 = tile[row * 64 + 32 + lane];
        float4 b0 = vn4[lane];
        float4 b1 = vn4[32 + lane];
        float p = a0.x * b0.x + a0.y * b0.y + a0.z * b0.z + a0.w * b0.w
                + a1.x * b1.x + a1.y * b1.y + a1.z * b1.z + a1.w * b1.w;
#pragma unroll
        for (int o = 16; o > 0; o >>= 1) p += __shfl_down_sync(0xffffffffu, p, o);
        if (lane == 0) dots[row] = p;
    }
    if (t == 0) {
        float s = 0.f;
#pragma unroll
        for (int i = 0; i < 8; i++) s += warp_part[i];
        s_selflogit = s;
    }
    __syncthreads();

    if (wid == 0) {
        float l  = fmaxf(dots[lane], 0.f);
        float l0 = fmaxf(s_selflogit, 0.f);
        float m = l;
#pragma unroll
        for (int o = 16; o > 0; o >>= 1) m = fmaxf(m, __shfl_xor_sync(0xffffffffu, m, o));
        m = fmaxf(m, l0);
        float e = expf(l - m);
        float ssum = e;
#pragma unroll
        for (int o = 16; o > 0; o >>= 1) ssum += __shfl_xor_sync(0xffffffffu, ssum, o);
        float denom = ssum + expf(l0 - m);
        float score = e / denom;

        int rank = 0;
#pragma unroll
        for (int j = 0; j < KNBR; j++) {
            float sj = __shfl_sync(0xffffffffu, score, j);
            rank += (sj > score) || (sj == score && j < lane);
        }
        if (rank < TOPK) { sel_w[rank] = score; sel_i[rank] = lane; }
    }
    __syncthreads();

    const float* ts = (const float*)tile;
    float acc = 0.f;
#pragma unroll
    for (int i = 0; i < TOPK; i++) acc += sel_w[i] * ts[sel_i[i] * D + t];
    g_Ah[(size_t)n * K2 + D + t] = __float2half_rn(acc);
}

// ---------------------------------------------------------------------------
// Phase 2: out = relu(A @ B^T), single-pass fp16, fp32 accum.
// BM=128, BN=128, BK=64, 8 warps (64x32 warp tiles), 3-stage cp.async,
// register-fragment double buffering across the 4 k16 steps.
// ---------------------------------------------------------------------------
#define BK    64
#define STG   36864                    // stage bytes: A 18432 + B 18432
#define AOF   0
#define B0OF  18432
#define GEMM_SMEM (3 * STG)            // 110592
#define NIT   8

__global__ void __launch_bounds__(256, 2)
gemm_kernel(float* __restrict__ out, int nrows)
{
    extern __shared__ uint8_t sm[];
    const uint32_t smb = smem_u32(sm);

    const int t    = threadIdx.x;
    const int wid  = t >> 5;
    const int lane = t & 31;
    const int row0 = blockIdx.x * 128;
    const int col0 = blockIdx.y * 128;
    const int wm   = (wid >> 2) * 64;    // 0/64
    const int wn   = (wid & 3) * 32;     // 0/32/64/96

    uint32_t offA[4];
#pragma unroll
    for (int i = 0; i < 4; i++)
        offA[i] = AOF + (uint32_t)(wm + i * 16 + (lane & 15)) * 144
                + (uint32_t)(((lane >> 4) << 3) * 2);
    uint32_t offB[2];
#pragma unroll
    for (int p = 0; p < 2; p++)
        offB[p] = (uint32_t)(wn + (2 * p + ((lane >> 3) >> 1)) * 8 + (lane & 7)) * 144
                + (uint32_t)(((lane >> 3) & 1) * 16);

    float acc[4][4][4];
#pragma unroll
    for (int i = 0; i < 4; i++)
#pragma unroll
        for (int j = 0; j < 4; j++)
#pragma unroll
            for (int q = 0; q < 4; q++) acc[i][j][q] = 0.f;

    auto prefetch = [&](int jt, int st) {
        const int koff = jt * BK;
        uint8_t* stage = sm + st * STG;
#pragma unroll
        for (int i = 0; i < 4; i++) {
            int idx = t + i * 256;
            int r = idx >> 3, c = idx & 7;
            uint32_t da = smem_u32(stage + AOF + r * 144 + c * 16);
            const void* sa = g_Ah + (size_t)(row0 + r) * K2 + koff + c * 8;
            asm volatile("cp.async.cg.shared.global [%0], [%1], 16;" :: "r"(da), "l"(sa));
        }
#pragma unroll
        for (int i = 0; i < 4; i++) {
            int idx = t + i * 256;
            int r = idx >> 3, c = idx & 7;
            uint32_t db = smem_u32(stage + B0OF + r * 144 + c * 16);
            const void* sb = g_Bh + (size_t)(col0 + r) * K2 + koff + c * 8;
            asm volatile("cp.async.cg.shared.global [%0], [%1], 16;" :: "r"(db), "l"(sb));
        }
        asm volatile("cp.async.commit_group;");
    };

    prefetch(0, 0);
    prefetch(1, 1);

    uint32_t a[2][4][4], b[2][4][2];

    auto ldfrag = [&](uint32_t sk, int pb) {
#pragma unroll
        for (int i = 0; i < 4; i++) {
            asm volatile("ldmatrix.sync.aligned.m8n8.x4.shared.b16 {%0,%1,%2,%3}, [%4];"
                         : "=r"(a[pb][i][0]), "=r"(a[pb][i][1]),
                           "=r"(a[pb][i][2]), "=r"(a[pb][i][3])
                         : "r"(sk + offA[i]));
        }
#pragma unroll
        for (int p = 0; p < 2; p++) {
            asm volatile("ldmatrix.sync.aligned.m8n8.x4.shared.b16 {%0,%1,%2,%3}, [%4];"
                         : "=r"(b[pb][2 * p][0]), "=r"(b[pb][2 * p][1]),
                           "=r"(b[pb][2 * p + 1][0]), "=r"(b[pb][2 * p + 1][1])
                         : "r"(sk + B0OF + offB[p]));
        }
    };

#pragma unroll 1
    for (int it = 0; it < NIT; it++) {
        asm volatile("cp.async.wait_group 1;");
        __syncthreads();                 // it-1 compute done before stage reuse below

        if (it + 2 < NIT) prefetch(it + 2, (it + 2) % 3);
        else asm volatile("cp.async.commit_group;");

        const uint32_t stage = smb + (uint32_t)((it % 3) * STG);

        ldfrag(stage, 0);
#pragma unroll
        for (int s = 0; s < 4; s++) {    // four k16 steps in BK=64
            const int cur = s & 1;
            if (s < 3) ldfrag(stage + (uint32_t)((s + 1) * 32), cur ^ 1);
#pragma unroll
            for (int i = 0; i < 4; i++)
#pragma unroll
                for (int j = 0; j < 4; j++) {
                    asm volatile(
                        "mma.sync.aligned.m16n8k16.row.col.f32.f16.f16.f32 "
                        "{%0,%1,%2,%3}, {%4,%5,%6,%7}, {%8,%9}, {%0,%1,%2,%3};"
                        : "+f"(acc[i][j][0]), "+f"(acc[i][j][1]),
                          "+f"(acc[i][j][2]), "+f"(acc[i][j][3])
                        : "r"(a[cur][i][0]), "r"(a[cur][i][1]),
                          "r"(a[cur][i][2]), "r"(a[cur][i][3]),
                          "r"(b[cur][j][0]), "r"(b[cur][j][1]));
                }
        }
    }

    __syncthreads();

    // epilogue: relu + store
#pragma unroll
    for (int i = 0; i < 4; i++) {
        int rA = row0 + wm + i * 16 + (lane >> 2);
        int rB = rA + 8;
#pragma unroll
        for (int j = 0; j < 4; j++) {
            int c = col0 + wn + j * 8 + (lane & 3) * 2;
            if (rA < nrows) {
                float2 v;
                v.x = fmaxf(acc[i][j][0], 0.f);
                v.y = fmaxf(acc[i][j][1], 0.f);
                *(float2*)&out[(size_t)rA * D + c] = v;
            }
            if (rB < nrows) {
                float2 v;
                v.x = fmaxf(acc[i][j][2], 0.f);
                v.y = fmaxf(acc[i][j][3], 0.f);
                *(float2*)&out[(size_t)rB * D + c] = v;
            }
        }
    }
}

// ---------------------------------------------------------------------------
extern "C" void kernel_launch(void* const* d_in, const int* in_sizes, int n_in,
                              void* d_out, int out_size)
{
    const float* self_vecs = (const float*)d_in[0];
    const float* neigh     = (const float*)d_in[1];
    const float* sw        = (const float*)d_in[2];
    const float* nw        = (const float*)d_in[3];
    const float* attn      = (const float*)d_in[4];
    float* out             = (float*)d_out;

    const int nrows = in_sizes[0] / D;   // 20000

    prep_kernel<<<16, 256>>>(sw, nw, attn);
    phase1_kernel<<<nrows, 256>>>(self_vecs, neigh, sw, nw);

    cudaFuncSetAttribute(gemm_kernel, cudaFuncAttributeMaxDynamicSharedMemorySize, GEMM_SMEM);
    dim3 g2((nrows + 127) / 128, 2);
    gemm_kernel<<<g2, 256, GEMM_SMEM>>>(out, nrows);
}

// round 15
// speedup vs baseline: 1.0231x; 1.0231x over previous
#include <cuda_runtime.h>
#include <cuda_fp16.h>
#include <math.h>
#include <stdint.h>

#define D      256
#define KNBR   32
#define TOPK   16
#define MAXN   20096      // 157 * 128, padded
#define K2     512        // GEMM K = 2*D

// ---------------- scratch (__device__ globals; zero-init, no allocs) -------
__device__ __align__(128) __half g_Ah[(size_t)MAXN * K2];  // [row, 512] fp16
__device__ __align__(128) __half g_Bh[D * K2];             // [n, 512] fp16 (W^T)
__device__ float g_vs[D];
__device__ float g_vn[D];

__device__ __forceinline__ uint32_t smem_u32(const void* p) {
    uint32_t a;
    asm("{ .reg .u64 t; cvta.to.shared.u64 t, %1; cvt.u32.u64 %0, t; }" : "=r"(a) : "l"(p));
    return a;
}

// ---------------------------------------------------------------------------
// prep: blocks 0..15 -> v = W @ a GEMV; blocks 16..527 -> convB fp16.
// ---------------------------------------------------------------------------
__global__ void __launch_bounds__(256)
prep_kernel(const float* __restrict__ sw, const float* __restrict__ nw,
            const float* __restrict__ attn)
{
    const int b = blockIdx.x;
    const int t = threadIdx.x;

    if (b < 16) {
        __shared__ float a[D];
        const int wid = t >> 5, lane = t & 31;
        a[t] = attn[t];
        __syncthreads();

        const float* w = ((b & 1) == 0) ? sw : nw;
#pragma unroll
        for (int r = 0; r < 4; r++) {
            int row = (b >> 1) * 32 + wid * 4 + r;
            const float4* wr = (const float4*)(w + (size_t)row * D);
            float4 v0 = wr[lane], v1 = wr[lane + 32];
            float p = v0.x * a[4 * lane + 0] + v0.y * a[4 * lane + 1]
                    + v0.z * a[4 * lane + 2] + v0.w * a[4 * lane + 3]
                    + v1.x * a[128 + 4 * lane + 0] + v1.y * a[128 + 4 * lane + 1]
                    + v1.z * a[128 + 4 * lane + 2] + v1.w * a[128 + 4 * lane + 3];
#pragma unroll
            for (int o = 16; o > 0; o >>= 1) p += __shfl_down_sync(0xffffffffu, p, o);
            if (lane == 0) { if ((b & 1) == 0) g_vs[row] = p; else g_vn[row] = p; }
        }
    } else {
        int idx = (b - 16) * 256 + t;                // 0 .. 131071
        int n = idx & 255;
        int k = idx >> 8;                            // 0 .. 511
        float w = (k < D) ? sw[(size_t)k * D + n] : nw[(size_t)(k - D) * D + n];
        g_Bh[(size_t)n * K2 + k] = __float2half_rn(w);
    }
}

// ---------------------------------------------------------------------------
// Phase 1: per node — logits, softmax over 33, top-16, weighted neighbor sum.
// cp.async tile load overlapped with self-row processing. Writes A fp16.
// ---------------------------------------------------------------------------
__global__ void __launch_bounds__(256)
phase1_kernel(const float* __restrict__ self_vecs,
              const float* __restrict__ neigh_vecs)
{
    __shared__ float4 tile[KNBR * D / 4];   // 32 KB
    __shared__ float4 vn4[D / 4];
    __shared__ float  dots[KNBR];
    __shared__ float  warp_part[8];
    __shared__ float  s_selflogit;
    __shared__ float  sel_w[TOPK];
    __shared__ int    sel_i[TOPK];

    const int n    = blockIdx.x;
    const int t    = threadIdx.x;
    const int wid  = t >> 5;
    const int lane = t & 31;

    const float4* src = (const float4*)(neigh_vecs + (size_t)n * KNBR * D);
#pragma unroll
    for (int i = 0; i < 8; i++) {
        uint32_t dst = smem_u32(&tile[t + 256 * i]);
        asm volatile("cp.async.cg.shared.global [%0], [%1], 16;"
                     :: "r"(dst), "l"((const void*)(src + t + 256 * i)));
    }
    asm volatile("cp.async.commit_group;");

    if (t < D / 4) vn4[t] = ((const float4*)g_vn)[t];

    float sv = self_vecs[(size_t)n * D + t];
    g_Ah[(size_t)n * K2 + t] = __float2half_rn(sv);
    float sp = sv * g_vs[t];
#pragma unroll
    for (int o = 16; o > 0; o >>= 1) sp += __shfl_down_sync(0xffffffffu, sp, o);
    if (lane == 0) warp_part[wid] = sp;

    asm volatile("cp.async.wait_group 0;");
    __syncthreads();

#pragma unroll
    for (int r = 0; r < 4; r++) {
        int row = wid * 4 + r;
        float4 a0 = tile[row * 64 + lane];
        float4 a1 = tile[row * 64 + 32 + lane];
        float4 b0 = vn4[lane];
        float4 b1 = vn4[32 + lane];
        float p = a0.x * b0.x + a0.y * b0.y + a0.z * b0.z + a0.w * b0.w
                + a1.x * b1.x + a1.y * b1.y + a1.z * b1.z + a1.w * b1.w;
#pragma unroll
        for (int o = 16; o > 0; o >>= 1) p += __shfl_down_sync(0xffffffffu, p, o);
        if (lane == 0) dots[row] = p;
    }
    if (t == 0) {
        float s = 0.f;
#pragma unroll
        for (int i = 0; i < 8; i++) s += warp_part[i];
        s_selflogit = s;
    }
    __syncthreads();

    if (wid == 0) {
        float l  = fmaxf(dots[lane], 0.f);
        float l0 = fmaxf(s_selflogit, 0.f);
        float m = l;
#pragma unroll
        for (int o = 16; o > 0; o >>= 1) m = fmaxf(m, __shfl_xor_sync(0xffffffffu, m, o));
        m = fmaxf(m, l0);
        float e = expf(l - m);
        float ssum = e;
#pragma unroll
        for (int o = 16; o > 0; o >>= 1) ssum += __shfl_xor_sync(0xffffffffu, ssum, o);
        float denom = ssum + expf(l0 - m);
        float score = e / denom;

        int rank = 0;
#pragma unroll
        for (int j = 0; j < KNBR; j++) {
            float sj = __shfl_sync(0xffffffffu, score, j);
            rank += (sj > score) || (sj == score && j < lane);
        }
        if (rank < TOPK) { sel_w[rank] = score; sel_i[rank] = lane; }
    }
    __syncthreads();

    const float* ts = (const float*)tile;
    float acc = 0.f;
#pragma unroll
    for (int i = 0; i < TOPK; i++) acc += sel_w[i] * ts[sel_i[i] * D + t];
    g_Ah[(size_t)n * K2 + D + t] = __float2half_rn(acc);
}

// ---------------------------------------------------------------------------
// Phase 2: out = relu(A @ B^T), single-pass fp16, fp32 accum.
// BM=128, BN=128, BK=64, 8 warps (64x32 warp tiles), 3-stage cp.async,
// single __syncthreads per iteration. Grid = (157, 2) -> 314 CTAs (~1 wave).
// ---------------------------------------------------------------------------
#define BK    64
#define STG   36864                    // stage bytes: A 18432 + B 18432
#define AOF   0
#define B0OF  18432
#define GEMM_SMEM (3 * STG)            // 110592
#define NIT   8

__global__ void __launch_bounds__(256)
gemm_kernel(float* __restrict__ out, int nrows)
{
    extern __shared__ uint8_t sm[];
    const uint32_t smb = smem_u32(sm);

    const int t    = threadIdx.x;
    const int wid  = t >> 5;
    const int lane = t & 31;
    const int row0 = blockIdx.x * 128;
    const int col0 = blockIdx.y * 128;
    const int wm   = (wid >> 2) * 64;    // 0/64
    const int wn   = (wid & 3) * 32;     // 0/32/64/96

    uint32_t offA[4];
#pragma unroll
    for (int i = 0; i < 4; i++)
        offA[i] = AOF + (uint32_t)(wm + i * 16 + (lane & 15)) * 144
                + (uint32_t)(((lane >> 4) << 3) * 2);
    uint32_t offB[2];
#pragma unroll
    for (int p = 0; p < 2; p++)
        offB[p] = (uint32_t)(wn + (2 * p + ((lane >> 3) >> 1)) * 8 + (lane & 7)) * 144
                + (uint32_t)(((lane >> 3) & 1) * 16);

    float acc[4][4][4];
#pragma unroll
    for (int i = 0; i < 4; i++)
#pragma unroll
        for (int j = 0; j < 4; j++)
#pragma unroll
            for (int q = 0; q < 4; q++) acc[i][j][q] = 0.f;

    auto prefetch = [&](int jt, int st) {
        const int koff = jt * BK;
        uint8_t* stage = sm + st * STG;
#pragma unroll
        for (int i = 0; i < 4; i++) {
            int idx = t + i * 256;
            int r = idx >> 3, c = idx & 7;
            uint32_t da = smem_u32(stage + AOF + r * 144 + c * 16);
            const void* sa = g_Ah + (size_t)(row0 + r) * K2 + koff + c * 8;
            asm volatile("cp.async.cg.shared.global [%0], [%1], 16;" :: "r"(da), "l"(sa));
        }
#pragma unroll
        for (int i = 0; i < 4; i++) {
            int idx = t + i * 256;
            int r = idx >> 3, c = idx & 7;
            uint32_t db = smem_u32(stage + B0OF + r * 144 + c * 16);
            const void* sb = g_Bh + (size_t)(col0 + r) * K2 + koff + c * 8;
            asm volatile("cp.async.cg.shared.global [%0], [%1], 16;" :: "r"(db), "l"(sb));
        }
        asm volatile("cp.async.commit_group;");
    };

    prefetch(0, 0);
    prefetch(1, 1);

#pragma unroll 1
    for (int it = 0; it < NIT; it++) {
        asm volatile("cp.async.wait_group 1;");
        __syncthreads();                 // it-1 compute done before stage reuse below

        if (it + 2 < NIT) prefetch(it + 2, (it + 2) % 3);
        else asm volatile("cp.async.commit_group;");

        const uint32_t stage = smb + (uint32_t)((it % 3) * STG);

#pragma unroll
        for (int s = 0; s < 4; s++) {    // four k16 steps in BK=64
            const uint32_t sk = stage + (uint32_t)(s * 32);
            uint32_t a[4][4], b[4][2];
#pragma unroll
            for (int i = 0; i < 4; i++) {
                asm volatile("ldmatrix.sync.aligned.m8n8.x4.shared.b16 {%0,%1,%2,%3}, [%4];"
                             : "=r"(a[i][0]), "=r"(a[i][1]), "=r"(a[i][2]), "=r"(a[i][3])
                             : "r"(sk + offA[i]));
            }
#pragma unroll
            for (int p = 0; p < 2; p++) {
                asm volatile("ldmatrix.sync.aligned.m8n8.x4.shared.b16 {%0,%1,%2,%3}, [%4];"
                             : "=r"(b[2 * p][0]), "=r"(b[2 * p][1]),
                               "=r"(b[2 * p + 1][0]), "=r"(b[2 * p + 1][1])
                             : "r"(sk + B0OF + offB[p]));
            }
#pragma unroll
            for (int i = 0; i < 4; i++)
#pragma unroll
                for (int j = 0; j < 4; j++) {
                    asm volatile(
                        "mma.sync.aligned.m16n8k16.row.col.f32.f16.f16.f32 "
                        "{%0,%1,%2,%3}, {%4,%5,%6,%7}, {%8,%9}, {%0,%1,%2,%3};"
                        : "+f"(acc[i][j][0]), "+f"(acc[i][j][1]),
                          "+f"(acc[i][j][2]), "+f"(acc[i][j][3])
                        : "r"(a[i][0]), "r"(a[i][1]), "r"(a[i][2]), "r"(a[i][3]),
                          "r"(b[j][0]), "r"(b[j][1]));
                }
        }
    }

    __syncthreads();

    // epilogue: relu + store
#pragma unroll
    for (int i = 0; i < 4; i++) {
        int rA = row0 + wm + i * 16 + (lane >> 2);
        int rB = rA + 8;
#pragma unroll
        for (int j = 0; j < 4; j++) {
            int c = col0 + wn + j * 8 + (lane & 3) * 2;
            if (rA < nrows) {
                float2 v;
                v.x = fmaxf(acc[i][j][0], 0.f);
                v.y = fmaxf(acc[i][j][1], 0.f);
                *(float2*)&out[(size_t)rA * D + c] = v;
            }
            if (rB < nrows) {
                float2 v;
                v.x = fmaxf(acc[i][j][2], 0.f);
                v.y = fmaxf(acc[i][j][3], 0.f);
                *(float2*)&out[(size_t)rB * D + c] = v;
            }
        }
    }
}

// ---------------------------------------------------------------------------
extern "C" void kernel_launch(void* const* d_in, const int* in_sizes, int n_in,
                              void* d_out, int out_size)
{
    const float* self_vecs = (const float*)d_in[0];
    const float* neigh     = (const float*)d_in[1];
    const float* sw        = (const float*)d_in[2];
    const float* nw        = (const float*)d_in[3];
    const float* attn      = (const float*)d_in[4];
    float* out             = (float*)d_out;

    const int nrows = in_sizes[0] / D;   // 20000

    prep_kernel<<<16 + (D * K2) / 256, 256>>>(sw, nw, attn);
    phase1_kernel<<<nrows, 256>>>(self_vecs, neigh);

    cudaFuncSetAttribute(gemm_kernel, cudaFuncAttributeMaxDynamicSharedMemorySize, GEMM_SMEM);
    dim3 g2((nrows + 127) / 128, 2);
    gemm_kernel<<<g2, 256, GEMM_SMEM>>>(out, nrows);
}

// round 16
// speedup vs baseline: 1.0284x; 1.0052x over previous
#include <cuda_runtime.h>
#include <cuda_fp16.h>
#include <math.h>
#include <stdint.h>

#define D      256
#define KNBR   32
#define TOPK   16
#define MAXN   20096      // 157 * 128, padded
#define K2     512        // GEMM K = 2*D

// ---------------- scratch (__device__ globals; zero-init, no allocs) -------
__device__ __align__(128) __half g_Ah[(size_t)MAXN * K2];  // [row, 512] fp16
__device__ __align__(128) __half g_Bh[D * K2];             // [n, 512] fp16 (W^T)
__device__ float g_vs[D];
__device__ float g_vn[D];

__device__ __forceinline__ uint32_t smem_u32(const void* p) {
    uint32_t a;
    asm("{ .reg .u64 t; cvta.to.shared.u64 t, %1; cvt.u32.u64 %0, t; }" : "=r"(a) : "l"(p));
    return a;
}

// ---------------------------------------------------------------------------
// prep: blocks 0..15 -> v = W @ a GEMV; blocks 16..527 -> convB fp16.
// ---------------------------------------------------------------------------
__global__ void __launch_bounds__(256)
prep_kernel(const float* __restrict__ sw, const float* __restrict__ nw,
            const float* __restrict__ attn)
{
    const int b = blockIdx.x;
    const int t = threadIdx.x;

    if (b < 16) {
        __shared__ float a[D];
        const int wid = t >> 5, lane = t & 31;
        a[t] = attn[t];
        __syncthreads();

        const float* w = ((b & 1) == 0) ? sw : nw;
#pragma unroll
        for (int r = 0; r < 4; r++) {
            int row = (b >> 1) * 32 + wid * 4 + r;
            const float4* wr = (const float4*)(w + (size_t)row * D);
            float4 v0 = wr[lane], v1 = wr[lane + 32];
            float p = v0.x * a[4 * lane + 0] + v0.y * a[4 * lane + 1]
                    + v0.z * a[4 * lane + 2] + v0.w * a[4 * lane + 3]
                    + v1.x * a[128 + 4 * lane + 0] + v1.y * a[128 + 4 * lane + 1]
                    + v1.z * a[128 + 4 * lane + 2] + v1.w * a[128 + 4 * lane + 3];
#pragma unroll
            for (int o = 16; o > 0; o >>= 1) p += __shfl_down_sync(0xffffffffu, p, o);
            if (lane == 0) { if ((b & 1) == 0) g_vs[row] = p; else g_vn[row] = p; }
        }
    } else {
        int idx = (b - 16) * 256 + t;                // 0 .. 131071
        int n = idx & 255;
        int k = idx >> 8;                            // 0 .. 511
        float w = (k < D) ? sw[(size_t)k * D + n] : nw[(size_t)(k - D) * D + n];
        g_Bh[(size_t)n * K2 + k] = __float2half_rn(w);
    }
}

// ---------------------------------------------------------------------------
// Phase 1: per node — logits, softmax over 33, top-16, weighted neighbor sum.
// cp.async tile load overlapped with self-row processing. Writes A fp16.
// v_neigh kept in registers (no vn4 SMEM) -> 33.1 KB/CTA -> 7 CTAs/SM.
// ---------------------------------------------------------------------------
__global__ void __launch_bounds__(256, 7)
phase1_kernel(const float* __restrict__ self_vecs,
              const float* __restrict__ neigh_vecs)
{
    __shared__ float4 tile[KNBR * D / 4];   // 32 KB
    __shared__ float  dots[KNBR];
    __shared__ float  warp_part[8];
    __shared__ float  s_selflogit;
    __shared__ float  sel_w[TOPK];
    __shared__ int    sel_i[TOPK];

    const int n    = blockIdx.x;
    const int t    = threadIdx.x;
    const int wid  = t >> 5;
    const int lane = t & 31;

    const float4* src = (const float4*)(neigh_vecs + (size_t)n * KNBR * D);
#pragma unroll
    for (int i = 0; i < 8; i++) {
        uint32_t dst = smem_u32(&tile[t + 256 * i]);
        asm volatile("cp.async.cg.shared.global [%0], [%1], 16;"
                     :: "r"(dst), "l"((const void*)(src + t + 256 * i)));
    }
    asm volatile("cp.async.commit_group;");

    // v_neigh fragments in registers (each lane's two float4s; L2-resident)
    const float4 vb0 = ((const float4*)g_vn)[lane];
    const float4 vb1 = ((const float4*)g_vn)[32 + lane];

    float sv = self_vecs[(size_t)n * D + t];
    g_Ah[(size_t)n * K2 + t] = __float2half_rn(sv);
    float sp = sv * g_vs[t];
#pragma unroll
    for (int o = 16; o > 0; o >>= 1) sp += __shfl_down_sync(0xffffffffu, sp, o);
    if (lane == 0) warp_part[wid] = sp;

    asm volatile("cp.async.wait_group 0;");
    __syncthreads();

#pragma unroll
    for (int r = 0; r < 4; r++) {
        int row = wid * 4 + r;
        float4 a0 = tile[row * 64 + lane];
        float4 a1 = tile[row * 64 + 32 + lane];
        float p = a0.x * vb0.x + a0.y * vb0.y + a0.z * vb0.z + a0.w * vb0.w
                + a1.x * vb1.x + a1.y * vb1.y + a1.z * vb1.z + a1.w * vb1.w;
#pragma unroll
        for (int o = 16; o > 0; o >>= 1) p += __shfl_down_sync(0xffffffffu, p, o);
        if (lane == 0) dots[row] = p;
    }
    if (t == 0) {
        float s = 0.f;
#pragma unroll
        for (int i = 0; i < 8; i++) s += warp_part[i];
        s_selflogit = s;
    }
    __syncthreads();

    if (wid == 0) {
        float l  = fmaxf(dots[lane], 0.f);
        float l0 = fmaxf(s_selflogit, 0.f);
        float m = l;
#pragma unroll
        for (int o = 16; o > 0; o >>= 1) m = fmaxf(m, __shfl_xor_sync(0xffffffffu, m, o));
        m = fmaxf(m, l0);
        float e = expf(l - m);
        float ssum = e;
#pragma unroll
        for (int o = 16; o > 0; o >>= 1) ssum += __shfl_xor_sync(0xffffffffu, ssum, o);
        float denom = ssum + expf(l0 - m);
        float score = e / denom;

        int rank = 0;
#pragma unroll
        for (int j = 0; j < KNBR; j++) {
            float sj = __shfl_sync(0xffffffffu, score, j);
            rank += (sj > score) || (sj == score && j < lane);
        }
        if (rank < TOPK) { sel_w[rank] = score; sel_i[rank] = lane; }
    }
    __syncthreads();

    const float* ts = (const float*)tile;
    float acc = 0.f;
#pragma unroll
    for (int i = 0; i < TOPK; i++) acc += sel_w[i] * ts[sel_i[i] * D + t];
    g_Ah[(size_t)n * K2 + D + t] = __float2half_rn(acc);
}

// ---------------------------------------------------------------------------
// Phase 2: out = relu(A @ B^T), single-pass fp16, fp32 accum.
// BM=128, BN=128, BK=64, 8 warps (64x32 warp tiles), 3-stage cp.async,
// single __syncthreads per iteration. Grid = (157, 2) -> 314 CTAs (~1 wave).
// ---------------------------------------------------------------------------
#define BK    64
#define STG   36864                    // stage bytes: A 18432 + B 18432
#define AOF   0
#define B0OF  18432
#define GEMM_SMEM (3 * STG)            // 110592
#define NIT   8

__global__ void __launch_bounds__(256)
gemm_kernel(float* __restrict__ out, int nrows)
{
    extern __shared__ uint8_t sm[];
    const uint32_t smb = smem_u32(sm);

    const int t    = threadIdx.x;
    const int wid  = t >> 5;
    const int lane = t & 31;
    const int row0 = blockIdx.x * 128;
    const int col0 = blockIdx.y * 128;
    const int wm   = (wid >> 2) * 64;    // 0/64
    const int wn   = (wid & 3) * 32;     // 0/32/64/96

    uint32_t offA[4];
#pragma unroll
    for (int i = 0; i < 4; i++)
        offA[i] = AOF + (uint32_t)(wm + i * 16 + (lane & 15)) * 144
                + (uint32_t)(((lane >> 4) << 3) * 2);
    uint32_t offB[2];
#pragma unroll
    for (int p = 0; p < 2; p++)
        offB[p] = (uint32_t)(wn + (2 * p + ((lane >> 3) >> 1)) * 8 + (lane & 7)) * 144
                + (uint32_t)(((lane >> 3) & 1) * 16);

    float acc[4][4][4];
#pragma unroll
    for (int i = 0; i < 4; i++)
#pragma unroll
        for (int j = 0; j < 4; j++)
#pragma unroll
            for (int q = 0; q < 4; q++) acc[i][j][q] = 0.f;

    auto prefetch = [&](int jt, int st) {
        const int koff = jt * BK;
        uint8_t* stage = sm + st * STG;
#pragma unroll
        for (int i = 0; i < 4; i++) {
            int idx = t + i * 256;
            int r = idx >> 3, c = idx & 7;
            uint32_t da = smem_u32(stage + AOF + r * 144 + c * 16);
            const void* sa = g_Ah + (size_t)(row0 + r) * K2 + koff + c * 8;
            asm volatile("cp.async.cg.shared.global [%0], [%1], 16;" :: "r"(da), "l"(sa));
        }
#pragma unroll
        for (int i = 0; i < 4; i++) {
            int idx = t + i * 256;
            int r = idx >> 3, c = idx & 7;
            uint32_t db = smem_u32(stage + B0OF + r * 144 + c * 16);
            const void* sb = g_Bh + (size_t)(col0 + r) * K2 + koff + c * 8;
            asm volatile("cp.async.cg.shared.global [%0], [%1], 16;" :: "r"(db), "l"(sb));
        }
        asm volatile("cp.async.commit_group;");
    };

    prefetch(0, 0);
    prefetch(1, 1);

#pragma unroll 1
    for (int it = 0; it < NIT; it++) {
        asm volatile("cp.async.wait_group 1;");
        __syncthreads();                 // it-1 compute done before stage reuse below

        if (it + 2 < NIT) prefetch(it + 2, (it + 2) % 3);
        else asm volatile("cp.async.commit_group;");

        const uint32_t stage = smb + (uint32_t)((it % 3) * STG);

#pragma unroll
        for (int s = 0; s < 4; s++) {    // four k16 steps in BK=64
            const uint32_t sk = stage + (uint32_t)(s * 32);
            uint32_t a[4][4], b[4][2];
#pragma unroll
            for (int i = 0; i < 4; i++) {
                asm volatile("ldmatrix.sync.aligned.m8n8.x4.shared.b16 {%0,%1,%2,%3}, [%4];"
                             : "=r"(a[i][0]), "=r"(a[i][1]), "=r"(a[i][2]), "=r"(a[i][3])
                             : "r"(sk + offA[i]));
            }
#pragma unroll
            for (int p = 0; p < 2; p++) {
                asm volatile("ldmatrix.sync.aligned.m8n8.x4.shared.b16 {%0,%1,%2,%3}, [%4];"
                             : "=r"(b[2 * p][0]), "=r"(b[2 * p][1]),
                               "=r"(b[2 * p + 1][0]), "=r"(b[2 * p + 1][1])
                             : "r"(sk + B0OF + offB[p]));
            }
#pragma unroll
            for (int i = 0; i < 4; i++)
#pragma unroll
                for (int j = 0; j < 4; j++) {
                    asm volatile(
                        "mma.sync.aligned.m16n8k16.row.col.f32.f16.f16.f32 "
                        "{%0,%1,%2,%3}, {%4,%5,%6,%7}, {%8,%9}, {%0,%1,%2,%3};"
                        : "+f"(acc[i][j][0]), "+f"(acc[i][j][1]),
                          "+f"(acc[i][j][2]), "+f"(acc[i][j][3])
                        : "r"(a[i][0]), "r"(a[i][1]), "r"(a[i][2]), "r"(a[i][3]),
                          "r"(b[j][0]), "r"(b[j][1]));
                }
        }
    }

    __syncthreads();

    // epilogue: relu + store
#pragma unroll
    for (int i = 0; i < 4; i++) {
        int rA = row0 + wm + i * 16 + (lane >> 2);
        int rB = rA + 8;
#pragma unroll
        for (int j = 0; j < 4; j++) {
            int c = col0 + wn + j * 8 + (lane & 3) * 2;
            if (rA < nrows) {
                float2 v;
                v.x = fmaxf(acc[i][j][0], 0.f);
                v.y = fmaxf(acc[i][j][1], 0.f);
                *(float2*)&out[(size_t)rA * D + c] = v;
            }
            if (rB < nrows) {
                float2 v;
                v.x = fmaxf(acc[i][j][2], 0.f);
                v.y = fmaxf(acc[i][j][3], 0.f);
                *(float2*)&out[(size_t)rB * D + c] = v;
            }
        }
    }
}

// ---------------------------------------------------------------------------
extern "C" void kernel_launch(void* const* d_in, const int* in_sizes, int n_in,
                              void* d_out, int out_size)
{
    const float* self_vecs = (const float*)d_in[0];
    const float* neigh     = (const float*)d_in[1];
    const float* sw        = (const float*)d_in[2];
    const float* nw        = (const float*)d_in[3];
    const float* attn      = (const float*)d_in[4];
    float* out             = (float*)d_out;

    const int nrows = in_sizes[0] / D;   // 20000

    prep_kernel<<<16 + (D * K2) / 256, 256>>>(sw, nw, attn);
    phase1_kernel<<<nrows, 256>>>(self_vecs, neigh);

    cudaFuncSetAttribute(gemm_kernel, cudaFuncAttributeMaxDynamicSharedMemorySize, GEMM_SMEM);
    dim3 g2((nrows + 127) / 128, 2);
    gemm_kernel<<<g2, 256, GEMM_SMEM>>>(out, nrows);
}

// round 17
// speedup vs baseline: 1.0912x; 1.0610x over previous
#include <cuda_runtime.h>
#include <cuda_fp16.h>
#include <math.h>
#include <stdint.h>

#define D      256
#define KNBR   32
#define TOPK   16
#define MAXN   20096      // 157 * 128, padded
#define K2     512        // GEMM K = 2*D

// ---------------- scratch (__device__ globals; zero-init, no allocs) -------
__device__ __align__(128) __half g_Ah[(size_t)MAXN * K2];  // [row, 512] fp16
__device__ __align__(128) __half g_Bh[D * K2];             // [n, 512] fp16 (W^T)
__device__ float g_vs[D];
__device__ float g_vn[D];

__device__ __forceinline__ uint32_t smem_u32(const void* p) {
    uint32_t a;
    asm("{ .reg .u64 t; cvta.to.shared.u64 t, %1; cvt.u32.u64 %0, t; }" : "=r"(a) : "l"(p));
    return a;
}

// ---------------------------------------------------------------------------
// prep: blocks 0..15 -> v = W @ a GEMV; blocks 16..527 -> convB fp16.
// ---------------------------------------------------------------------------
__global__ void __launch_bounds__(256)
prep_kernel(const float* __restrict__ sw, const float* __restrict__ nw,
            const float* __restrict__ attn)
{
    const int b = blockIdx.x;
    const int t = threadIdx.x;

    if (b < 16) {
        __shared__ float a[D];
        const int wid = t >> 5, lane = t & 31;
        a[t] = attn[t];
        __syncthreads();

        const float* w = ((b & 1) == 0) ? sw : nw;
#pragma unroll
        for (int r = 0; r < 4; r++) {
            int row = (b >> 1) * 32 + wid * 4 + r;
            const float4* wr = (const float4*)(w + (size_t)row * D);
            float4 v0 = wr[lane], v1 = wr[lane + 32];
            float p = v0.x * a[4 * lane + 0] + v0.y * a[4 * lane + 1]
                    + v0.z * a[4 * lane + 2] + v0.w * a[4 * lane + 3]
                    + v1.x * a[128 + 4 * lane + 0] + v1.y * a[128 + 4 * lane + 1]
                    + v1.z * a[128 + 4 * lane + 2] + v1.w * a[128 + 4 * lane + 3];
#pragma unroll
            for (int o = 16; o > 0; o >>= 1) p += __shfl_down_sync(0xffffffffu, p, o);
            if (lane == 0) { if ((b & 1) == 0) g_vs[row] = p; else g_vn[row] = p; }
        }
    } else {
        int idx = (b - 16) * 256 + t;                // 0 .. 131071
        int n = idx & 255;
        int k = idx >> 8;                            // 0 .. 511
        float w = (k < D) ? sw[(size_t)k * D + n] : nw[(size_t)(k - D) * D + n];
        g_Bh[(size_t)n * K2 + k] = __float2half_rn(w);
    }
}

// ---------------------------------------------------------------------------
// Phase 1: per node — logits, softmax over 33, top-16, weighted neighbor sum.
// cp.async tile load (L2::evict_first — read-once stream, keep L2 clean for
// g_Ah) overlapped with self-row processing. v_neigh in registers; 7 CTAs/SM.
// ---------------------------------------------------------------------------
__global__ void __launch_bounds__(256, 7)
phase1_kernel(const float* __restrict__ self_vecs,
              const float* __restrict__ neigh_vecs)
{
    __shared__ float4 tile[KNBR * D / 4];   // 32 KB
    __shared__ float  dots[KNBR];
    __shared__ float  warp_part[8];
    __shared__ float  s_selflogit;
    __shared__ float  sel_w[TOPK];
    __shared__ int    sel_i[TOPK];

    const int n    = blockIdx.x;
    const int t    = threadIdx.x;
    const int wid  = t >> 5;
    const int lane = t & 31;

    // evict-first policy for the read-once neighbor stream
    uint64_t pol;
    asm volatile("createpolicy.fractional.L2::evict_first.b64 %0, 1.0;" : "=l"(pol));

    const float4* src = (const float4*)(neigh_vecs + (size_t)n * KNBR * D);
#pragma unroll
    for (int i = 0; i < 8; i++) {
        uint32_t dst = smem_u32(&tile[t + 256 * i]);
        asm volatile("cp.async.cg.shared.global.L2::cache_hint [%0], [%1], 16, %2;"
                     :: "r"(dst), "l"((const void*)(src + t + 256 * i)), "l"(pol));
    }
    asm volatile("cp.async.commit_group;");

    // v_neigh fragments in registers (each lane's two float4s; L2-resident)
    const float4 vb0 = ((const float4*)g_vn)[lane];
    const float4 vb1 = ((const float4*)g_vn)[32 + lane];

    float sv = self_vecs[(size_t)n * D + t];
    g_Ah[(size_t)n * K2 + t] = __float2half_rn(sv);
    float sp = sv * g_vs[t];
#pragma unroll
    for (int o = 16; o > 0; o >>= 1) sp += __shfl_down_sync(0xffffffffu, sp, o);
    if (lane == 0) warp_part[wid] = sp;

    asm volatile("cp.async.wait_group 0;");
    __syncthreads();

#pragma unroll
    for (int r = 0; r < 4; r++) {
        int row = wid * 4 + r;
        float4 a0 = tile[row * 64 + lane];
        float4 a1 = tile[row * 64 + 32 + lane];
        float p = a0.x * vb0.x + a0.y * vb0.y + a0.z * vb0.z + a0.w * vb0.w
                + a1.x * vb1.x + a1.y * vb1.y + a1.z * vb1.z + a1.w * vb1.w;
#pragma unroll
        for (int o = 16; o > 0; o >>= 1) p += __shfl_down_sync(0xffffffffu, p, o);
        if (lane == 0) dots[row] = p;
    }
    if (t == 0) {
        float s = 0.f;
#pragma unroll
        for (int i = 0; i < 8; i++) s += warp_part[i];
        s_selflogit = s;
    }
    __syncthreads();

    if (wid == 0) {
        float l  = fmaxf(dots[lane], 0.f);
        float l0 = fmaxf(s_selflogit, 0.f);
        float m = l;
#pragma unroll
        for (int o = 16; o > 0; o >>= 1) m = fmaxf(m, __shfl_xor_sync(0xffffffffu, m, o));
        m = fmaxf(m, l0);
        float e = expf(l - m);
        float ssum = e;
#pragma unroll
        for (int o = 16; o > 0; o >>= 1) ssum += __shfl_xor_sync(0xffffffffu, ssum, o);
        float denom = ssum + expf(l0 - m);
        float score = e / denom;

        int rank = 0;
#pragma unroll
        for (int j = 0; j < KNBR; j++) {
            float sj = __shfl_sync(0xffffffffu, score, j);
            rank += (sj > score) || (sj == score && j < lane);
        }
        if (rank < TOPK) { sel_w[rank] = score; sel_i[rank] = lane; }
    }
    __syncthreads();

    const float* ts = (const float*)tile;
    float acc = 0.f;
#pragma unroll
    for (int i = 0; i < TOPK; i++) acc += sel_w[i] * ts[sel_i[i] * D + t];
    g_Ah[(size_t)n * K2 + D + t] = __float2half_rn(acc);
}

// ---------------------------------------------------------------------------
// Phase 2: out = relu(A @ B^T), single-pass fp16, fp32 accum.
// BM=128, BN=128, BK=64, 8 warps (64x32 warp tiles), 3-stage cp.async,
// single __syncthreads per iteration. Grid = (157, 2) -> 314 CTAs (~1 wave).
// ---------------------------------------------------------------------------
#define BK    64
#define STG   36864                    // stage bytes: A 18432 + B 18432
#define AOF   0
#define B0OF  18432
#define GEMM_SMEM (3 * STG)            // 110592
#define NIT   8

__global__ void __launch_bounds__(256)
gemm_kernel(float* __restrict__ out, int nrows)
{
    extern __shared__ uint8_t sm[];
    const uint32_t smb = smem_u32(sm);

    const int t    = threadIdx.x;
    const int wid  = t >> 5;
    const int lane = t & 31;
    const int row0 = blockIdx.x * 128;
    const int col0 = blockIdx.y * 128;
    const int wm   = (wid >> 2) * 64;    // 0/64
    const int wn   = (wid & 3) * 32;     // 0/32/64/96

    uint32_t offA[4];
#pragma unroll
    for (int i = 0; i < 4; i++)
        offA[i] = AOF + (uint32_t)(wm + i * 16 + (lane & 15)) * 144
                + (uint32_t)(((lane >> 4) << 3) * 2);
    uint32_t offB[2];
#pragma unroll
    for (int p = 0; p < 2; p++)
        offB[p] = (uint32_t)(wn + (2 * p + ((lane >> 3) >> 1)) * 8 + (lane & 7)) * 144
                + (uint32_t)(((lane >> 3) & 1) * 16);

    float acc[4][4][4];
#pragma unroll
    for (int i = 0; i < 4; i++)
#pragma unroll
        for (int j = 0; j < 4; j++)
#pragma unroll
            for (int q = 0; q < 4; q++) acc[i][j][q] = 0.f;

    auto prefetch = [&](int jt, int st) {
        const int koff = jt * BK;
        uint8_t* stage = sm + st * STG;
#pragma unroll
        for (int i = 0; i < 4; i++) {
            int idx = t + i * 256;
            int r = idx >> 3, c = idx & 7;
            uint32_t da = smem_u32(stage + AOF + r * 144 + c * 16);
            const void* sa = g_Ah + (size_t)(row0 + r) * K2 + koff + c * 8;
            asm volatile("cp.async.cg.shared.global [%0], [%1], 16;" :: "r"(da), "l"(sa));
        }
#pragma unroll
        for (int i = 0; i < 4; i++) {
            int idx = t + i * 256;
            int r = idx >> 3, c = idx & 7;
            uint32_t db = smem_u32(stage + B0OF + r * 144 + c * 16);
            const void* sb = g_Bh + (size_t)(col0 + r) * K2 + koff + c * 8;
            asm volatile("cp.async.cg.shared.global [%0], [%1], 16;" :: "r"(db), "l"(sb));
        }
        asm volatile("cp.async.commit_group;");
    };

    prefetch(0, 0);
    prefetch(1, 1);

#pragma unroll 1
    for (int it = 0; it < NIT; it++) {
        asm volatile("cp.async.wait_group 1;");
        __syncthreads();                 // it-1 compute done before stage reuse below

        if (it + 2 < NIT) prefetch(it + 2, (it + 2) % 3);
        else asm volatile("cp.async.commit_group;");

        const uint32_t stage = smb + (uint32_t)((it % 3) * STG);

#pragma unroll
        for (int s = 0; s < 4; s++) {    // four k16 steps in BK=64
            const uint32_t sk = stage + (uint32_t)(s * 32);
            uint32_t a[4][4], b[4][2];
#pragma unroll
            for (int i = 0; i < 4; i++) {
                asm volatile("ldmatrix.sync.aligned.m8n8.x4.shared.b16 {%0,%1,%2,%3}, [%4];"
                             : "=r"(a[i][0]), "=r"(a[i][1]), "=r"(a[i][2]), "=r"(a[i][3])
                             : "r"(sk + offA[i]));
            }
#pragma unroll
            for (int p = 0; p < 2; p++) {
                asm volatile("ldmatrix.sync.aligned.m8n8.x4.shared.b16 {%0,%1,%2,%3}, [%4];"
                             : "=r"(b[2 * p][0]), "=r"(b[2 * p][1]),
                               "=r"(b[2 * p + 1][0]), "=r"(b[2 * p + 1][1])
                             : "r"(sk + B0OF + offB[p]));
            }
#pragma unroll
            for (int i = 0; i < 4; i++)
#pragma unroll
                for (int j = 0; j < 4; j++) {
                    asm volatile(
                        "mma.sync.aligned.m16n8k16.row.col.f32.f16.f16.f32 "
                        "{%0,%1,%2,%3}, {%4,%5,%6,%7}, {%8,%9}, {%0,%1,%2,%3};"
                        : "+f"(acc[i][j][0]), "+f"(acc[i][j][1]),
                          "+f"(acc[i][j][2]), "+f"(acc[i][j][3])
                        : "r"(a[i][0]), "r"(a[i][1]), "r"(a[i][2]), "r"(a[i][3]),
                          "r"(b[j][0]), "r"(b[j][1]));
                }
        }
    }

    __syncthreads();

    // epilogue: relu + store
#pragma unroll
    for (int i = 0; i < 4; i++) {
        int rA = row0 + wm + i * 16 + (lane >> 2);
        int rB = rA + 8;
#pragma unroll
        for (int j = 0; j < 4; j++) {
            int c = col0 + wn + j * 8 + (lane & 3) * 2;
            if (rA < nrows) {
                float2 v;
                v.x = fmaxf(acc[i][j][0], 0.f);
                v.y = fmaxf(acc[i][j][1], 0.f);
                *(float2*)&out[(size_t)rA * D + c] = v;
            }
            if (rB < nrows) {
                float2 v;
                v.x = fmaxf(acc[i][j][2], 0.f);
                v.y = fmaxf(acc[i][j][3], 0.f);
                *(float2*)&out[(size_t)rB * D + c] = v;
            }
        }
    }
}

// ---------------------------------------------------------------------------
extern "C" void kernel_launch(void* const* d_in, const int* in_sizes, int n_in,
                              void* d_out, int out_size)
{
    const float* self_vecs = (const float*)d_in[0];
    const float* neigh     = (const float*)d_in[1];
    const float* sw        = (const float*)d_in[2];
    const float* nw        = (const float*)d_in[3];
    const float* attn      = (const float*)d_in[4];
    float* out             = (float*)d_out;

    const int nrows = in_sizes[0] / D;   // 20000

    prep_kernel<<<16 + (D * K2) / 256, 256>>>(sw, nw, attn);
    phase1_kernel<<<nrows, 256>>>(self_vecs, neigh);

    cudaFuncSetAttribute(gemm_kernel, cudaFuncAttributeMaxDynamicSharedMemorySize, GEMM_SMEM);
    dim3 g2((nrows + 127) / 128, 2);
    gemm_kernel<<<g2, 256, GEMM_SMEM>>>(out, nrows);
}